// round 1
// baseline (speedup 1.0000x reference)
#include <cuda_runtime.h>
#include <cstdint>

// Problem constants
#define BB     4
#define S_TOT  5184
#define SS0    1088
#define SS1    4096
#define HH     1024
#define NHH    16
#define HDD    64

// Scratch (device globals; no allocation allowed)
__device__ float g_qkv0[(size_t)BB * SS0 * 3 * HH];   // 53.5 MB : q|k|v for text+32grid tokens
__device__ float g_qkv1[(size_t)BB * SS1 * 3 * HH];   // 201  MB : q|k|v for 64-grid tokens
__device__ float g_ctx [(size_t)BB * S_TOT * HH];     // 85   MB : concat(context0, context1)

// ---------------------------------------------------------------------------
// Generic fp32 GEMM: C[M,N] = gather_rows(A)[M,1024] @ W[1024,N] + bias[N]
// Row m of A maps to global row (m/seg_len)*S_TOT + seg_off + (m%seg_len),
// each A row is 1024 floats. 128x128x16 tiles, 256 threads, 8x8 microtile.
// ---------------------------------------------------------------------------
__global__ __launch_bounds__(256)
void gemm_kernel(const float* __restrict__ A, const float* __restrict__ W,
                 const float* __restrict__ bias, float* __restrict__ C,
                 int N, int seg_len, int seg_off)
{
    __shared__ float As[128][17];
    __shared__ float Bs[16][128];
    __shared__ int   rowoff[128];

    const int K = 1024;
    const int tid = threadIdx.x;
    const int m0 = blockIdx.y << 7;
    const int n0 = blockIdx.x << 7;

    if (tid < 128) {
        int m = m0 + tid;
        int grow = (m / seg_len) * S_TOT + seg_off + (m % seg_len);
        rowoff[tid] = grow * K;
    }
    __syncthreads();

    float acc[8][8];
#pragma unroll
    for (int i = 0; i < 8; i++)
#pragma unroll
        for (int j = 0; j < 8; j++) acc[i][j] = 0.f;

    const int tx = tid & 15, ty = tid >> 4;

    for (int k0 = 0; k0 < K; k0 += 16) {
#pragma unroll
        for (int r = 0; r < 8; r++) {
            int idx = tid + (r << 8);
            As[idx >> 4][idx & 15] = A[rowoff[idx >> 4] + k0 + (idx & 15)];
        }
#pragma unroll
        for (int r = 0; r < 8; r++) {
            int idx = tid + (r << 8);
            Bs[idx >> 7][idx & 127] =
                W[(size_t)(k0 + (idx >> 7)) * N + n0 + (idx & 127)];
        }
        __syncthreads();
#pragma unroll
        for (int kk = 0; kk < 16; kk++) {
            float a[8], b[8];
#pragma unroll
            for (int i = 0; i < 8; i++) a[i] = As[ty * 8 + i][kk];
            float4 b0 = *(const float4*)&Bs[kk][tx * 8];
            float4 b1 = *(const float4*)&Bs[kk][tx * 8 + 4];
            b[0] = b0.x; b[1] = b0.y; b[2] = b0.z; b[3] = b0.w;
            b[4] = b1.x; b[5] = b1.y; b[6] = b1.z; b[7] = b1.w;
#pragma unroll
            for (int i = 0; i < 8; i++)
#pragma unroll
                for (int j = 0; j < 8; j++)
                    acc[i][j] += a[i] * b[j];
        }
        __syncthreads();
    }

#pragma unroll
    for (int i = 0; i < 8; i++) {
        size_t m = (size_t)(m0 + ty * 8 + i);
#pragma unroll
        for (int j = 0; j < 8; j++) {
            int n = n0 + tx * 8 + j;
            C[m * N + n] = acc[i][j] + bias[n];
        }
    }
}

// ---------------------------------------------------------------------------
// Dense causal attention over S0=1088 tokens.
// Block = 8 warps, warp owns one query. Shared K/V tiles of 32 keys.
// Online softmax; masked scores are -10000 (matches reference), p forced 0.
// grid: (136 qtiles, 16 heads, 4 batches)
// ---------------------------------------------------------------------------
__global__ __launch_bounds__(256)
void attn0_kernel(const float* __restrict__ qkv, float* __restrict__ ctx)
{
    __shared__ float Ks[32][65];
    __shared__ float Vs[32][65];
    __shared__ float qs[8][66];
    __shared__ float ps[8][32];

    const int tid  = threadIdx.x;
    const int w    = tid >> 5, lane = tid & 31;
    const int qt   = blockIdx.x;
    const int h    = blockIdx.y;
    const int b    = blockIdx.z;

    const int qi = qt * 8 + w;
    const int c0 = lane * 2;

    {
        const float* qrow = qkv + ((size_t)(b * SS0 + qi)) * 3072 + h * 64;
        float2 qv = *(const float2*)(qrow + c0);
        qs[w][c0]     = qv.x * 0.125f;   // 1/sqrt(64)
        qs[w][c0 + 1] = qv.y * 0.125f;
    }
    __syncwarp();

    float m = -1e30f, l = 0.f, accx = 0.f, accy = 0.f;

    const int ntiles = (qt * 8 + 7) / 32 + 1;
    for (int t = 0; t < ntiles; t++) {
        const int j0 = t * 32;
        const float* kbase = qkv + ((size_t)(b * SS0 + j0)) * 3072 + 1024 + h * 64;
        const float* vbase = kbase + 1024;
        __syncthreads();
#pragma unroll
        for (int r = 0; r < 8; r++) {
            int idx = tid + (r << 8);
            int jj = idx >> 6, cc = idx & 63;
            Ks[jj][cc] = kbase[(size_t)jj * 3072 + cc];
            Vs[jj][cc] = vbase[(size_t)jj * 3072 + cc];
        }
        __syncthreads();

        // score for key j0+lane
        float s = 0.f;
#pragma unroll
        for (int cc = 0; cc < 64; cc++) s += qs[w][cc] * Ks[lane][cc];
        const int jg = j0 + lane;
        const bool ok = (jg <= qi);
        if (!ok) s = -10000.f;

        float mt = s;
#pragma unroll
        for (int d = 16; d; d >>= 1) mt = fmaxf(mt, __shfl_xor_sync(~0u, mt, d));
        const float mnew = fmaxf(m, mt);
        const float p = ok ? __expf(s - mnew) : 0.f;
        const float scale = __expf(m - mnew);
        float pt = p;
#pragma unroll
        for (int d = 16; d; d >>= 1) pt += __shfl_xor_sync(~0u, pt, d);
        l = l * scale + pt;
        accx *= scale; accy *= scale;
        m = mnew;
        ps[w][lane] = p;
        __syncwarp();
#pragma unroll
        for (int jj = 0; jj < 32; jj++) {
            const float pj = ps[w][jj];
            accx += pj * Vs[jj][c0];
            accy += pj * Vs[jj][c0 + 1];
        }
        __syncwarp();
    }
    const float inv = 1.f / l;
    float2 o; o.x = accx * inv; o.y = accy * inv;
    *(float2*)(ctx + ((size_t)(b * S_TOT + qi)) * 1024 + h * 64 + c0) = o;
}

// ---------------------------------------------------------------------------
// Local grid attention for the 64x64 tokens: 49 cross offsets (into 32x32
// K0/V0 grid via i//2 mapping) + 77 causal offsets (17x9 half-kernel).
// Warp per query position; OOB offsets contribute score 0 (zero padding).
// grid: (512 position-octets, 64 bh)
// ---------------------------------------------------------------------------
__global__ __launch_bounds__(256)
void attn1_kernel(const float* __restrict__ qkv0, const float* __restrict__ qkv1,
                  float* __restrict__ ctx)
{
    __shared__ float ss[8][128];

    const int tid  = threadIdx.x;
    const int w    = tid >> 5, lane = tid & 31;
    const int bh   = blockIdx.y;
    const int b    = bh >> 4, h = bh & 15;
    const int l    = blockIdx.x * 8 + w;
    const int i    = l >> 6, j = l & 63;
    const int c0   = lane * 2;

    float2 q = *(const float2*)(qkv1 + ((size_t)(b * SS1 + l)) * 3072 + h * 64 + c0);
    q.x *= 0.125f; q.y *= 0.125f;

    const float* k0base = qkv0 + ((size_t)(b * SS0 + 64)) * 3072 + 1024 + h * 64 + c0;
    const float* k1base = qkv1 + ((size_t)(b * SS1)) * 3072 + 1024 + h * 64 + c0;

    const int ci = i >> 1, cj = j >> 1;

    // ---- pass 1: scores ----
    int o = 0;
    for (int dy = -3; dy <= 3; dy++)
        for (int dx = -3; dx <= 3; dx++, o++) {
            const int iy = ci + dy, ix = cj + dx;
            float s = 0.f;
            if ((unsigned)iy < 32u && (unsigned)ix < 32u) {
                const float2 kv = *(const float2*)(k0base + (size_t)(iy * 32 + ix) * 3072);
                s = q.x * kv.x + q.y * kv.y;
#pragma unroll
                for (int d = 16; d; d >>= 1) s += __shfl_xor_sync(~0u, s, d);
            }
            if (lane == 0) ss[w][o] = s;
        }
    for (int dy = -8; dy <= 0; dy++) {
        const int dxmax = (dy == 0) ? 0 : 4;
        for (int dx = -4; dx <= dxmax; dx++, o++) {
            const int iy = i + dy, ix = j + dx;
            float s = 0.f;
            if ((unsigned)iy < 64u && (unsigned)ix < 64u) {
                const float2 kv = *(const float2*)(k1base + (size_t)(iy * 64 + ix) * 3072);
                s = q.x * kv.x + q.y * kv.y;
#pragma unroll
                for (int d = 16; d; d >>= 1) s += __shfl_xor_sync(~0u, s, d);
            }
            if (lane == 0) ss[w][o] = s;
        }
    }
    __syncwarp();

    // ---- softmax over 126 ----
    float sv[4];
#pragma unroll
    for (int g = 0; g < 4; g++) {
        const int oo = lane + 32 * g;
        sv[g] = (oo < 126) ? ss[w][oo] : -1e30f;
    }
    float mx = fmaxf(fmaxf(sv[0], sv[1]), fmaxf(sv[2], sv[3]));
#pragma unroll
    for (int d = 16; d; d >>= 1) mx = fmaxf(mx, __shfl_xor_sync(~0u, mx, d));
    float sum = 0.f, e[4];
#pragma unroll
    for (int g = 0; g < 4; g++) {
        const int oo = lane + 32 * g;
        e[g] = (oo < 126) ? __expf(sv[g] - mx) : 0.f;
        sum += e[g];
    }
#pragma unroll
    for (int d = 16; d; d >>= 1) sum += __shfl_xor_sync(~0u, sum, d);
    const float inv = 1.f / sum;
#pragma unroll
    for (int g = 0; g < 4; g++) {
        const int oo = lane + 32 * g;
        if (oo < 126) ss[w][oo] = e[g] * inv;
    }
    __syncwarp();

    // ---- pass 2: weighting ----
    const float* v0base = k0base + 1024;
    const float* v1base = k1base + 1024;
    float2 acc; acc.x = 0.f; acc.y = 0.f;
    o = 0;
    for (int dy = -3; dy <= 3; dy++)
        for (int dx = -3; dx <= 3; dx++, o++) {
            const int iy = ci + dy, ix = cj + dx;
            if ((unsigned)iy < 32u && (unsigned)ix < 32u) {
                const float p = ss[w][o];
                const float2 vv = *(const float2*)(v0base + (size_t)(iy * 32 + ix) * 3072);
                acc.x += p * vv.x;
                acc.y += p * vv.y;
            }
        }
    for (int dy = -8; dy <= 0; dy++) {
        const int dxmax = (dy == 0) ? 0 : 4;
        for (int dx = -4; dx <= dxmax; dx++, o++) {
            const int iy = i + dy, ix = j + dx;
            if ((unsigned)iy < 64u && (unsigned)ix < 64u) {
                const float p = ss[w][o];
                const float2 vv = *(const float2*)(v1base + (size_t)(iy * 64 + ix) * 3072);
                acc.x += p * vv.x;
                acc.y += p * vv.y;
            }
        }
    }

    *(float2*)(ctx + ((size_t)(b * S_TOT + SS0 + l)) * 1024 + h * 64 + c0) = acc;
}

// ---------------------------------------------------------------------------
extern "C" void kernel_launch(void* const* d_in, const int* in_sizes, int n_in,
                              void* d_out, int out_size)
{
    const float* hidden  = (const float*)d_in[0];
    // d_in[1] = mask (pure causal over S0; implemented implicitly)
    const float* W_qkv   = (const float*)d_in[2];
    const float* b_qkv   = (const float*)d_in[3];
    const float* W_qkvp  = (const float*)d_in[4];
    const float* b_qkvp  = (const float*)d_in[5];
    const float* W_dense = (const float*)d_in[6];
    const float* b_dense = (const float*)d_in[7];
    float* out = (float*)d_out;

    float *qkv0, *qkv1, *ctx;
    cudaGetSymbolAddress((void**)&qkv0, g_qkv0);
    cudaGetSymbolAddress((void**)&qkv1, g_qkv1);
    cudaGetSymbolAddress((void**)&ctx,  g_ctx);

    const dim3 blk(256);

    // QKV projections
    gemm_kernel<<<dim3(24, 34),  blk>>>(hidden, W_qkv,  b_qkv,  qkv0, 3072, SS0, 0);
    gemm_kernel<<<dim3(24, 128), blk>>>(hidden, W_qkvp, b_qkvp, qkv1, 3072, SS1, SS0);

    // Attention
    attn0_kernel<<<dim3(136, 16, 4), blk>>>(qkv0, ctx);
    attn1_kernel<<<dim3(512, 64),    blk>>>(qkv0, qkv1, ctx);

    // Output projection
    gemm_kernel<<<dim3(8, 162), blk>>>(ctx, W_dense, b_dense, out, 1024, 1 << 30, 0);
}

// round 11
// speedup vs baseline: 2.4852x; 2.4852x over previous
#include <cuda_runtime.h>
#include <cuda_bf16.h>
#include <cstdint>

// Problem constants
#define BB     4
#define S_TOT  5184
#define SS0    1088
#define SS1    4096
#define HH     1024
#define NHH    16
#define HDD    64

typedef __nv_bfloat16 bf16;

// ---------------- scratch (device globals; no allocation allowed) -------------
__device__ float g_qkv0[(size_t)BB * SS0 * 3 * HH];
__device__ float g_qkv1[(size_t)BB * SS1 * 3 * HH];
__device__ bf16  g_hid_hi[(size_t)BB * S_TOT * HH];
__device__ bf16  g_hid_lo[(size_t)BB * S_TOT * HH];
__device__ bf16  g_ctx_hi[(size_t)BB * S_TOT * HH];
__device__ bf16  g_ctx_lo[(size_t)BB * S_TOT * HH];
// transposed weights [N,K] K-major: rows 0..3071 qkv, 3072..6143 qkv_plus, 6144..7167 dense
__device__ bf16  g_Wt_hi[(size_t)7168 * 1024];
__device__ bf16  g_Wt_lo[(size_t)7168 * 1024];

// hi/lo split helper (identical math everywhere)
__device__ __forceinline__ void split_hl(float x, bf16& h, bf16& l) {
    h = __float2bfloat16(x);
    l = __float2bfloat16(x - __bfloat162float(h));
}

// m16n8k16 bf16 MMA, fp32 accumulate (sm_80+ baseline PTX — legal on plain sm_103)
#define MMA_BF16(d, a, b) \
    asm volatile("mma.sync.aligned.m16n8k16.row.col.f32.bf16.bf16.f32 " \
        "{%0,%1,%2,%3}, {%4,%5,%6,%7}, {%8,%9}, {%0,%1,%2,%3};" \
        : "+f"((d)[0]), "+f"((d)[1]), "+f"((d)[2]), "+f"((d)[3]) \
        : "r"((a)[0]), "r"((a)[1]), "r"((a)[2]), "r"((a)[3]), \
          "r"((b)[0]), "r"((b)[1]))

#define GEMM_RS    40                         // smem row stride (bf16 elems), padded
#define GEMM_ARR   (128 * GEMM_RS)            // one array (5120 elems)
#define GEMM_SMEM_BYTES (2 * 4 * GEMM_ARR * 2)  // 81920 B

// ---------------------------------------------------------------------------
// bf16 mma.sync GEMM: C[M,N] = gather_rows(A)[M,1024] @ Bt[N,1024]^T + bias[N]
// A as hi/lo bf16 [rows,1024]; Bt as hi/lo bf16 [N,1024] (K-major rows).
// 3-term split accumulation (hi*hi + hi*lo + lo*hi) in fp32 registers.
// 128x128 CTA tile, 8 warps (64x32 each), BK=32 double-buffered smem.
// ---------------------------------------------------------------------------
__global__ __launch_bounds__(256, 1)
void gemm_mma(const bf16* __restrict__ Ahi, const bf16* __restrict__ Alo,
              const bf16* __restrict__ Bhi, const bf16* __restrict__ Blo,
              const float* __restrict__ bias, float* __restrict__ C,
              int N, int seg_len, int seg_off)
{
    extern __shared__ bf16 sm[];   // [2 buf][4 arr: Ah,Al,Bh,Bl][128*GEMM_RS]

    const int tid  = threadIdx.x;
    const int w    = tid >> 5, lane = tid & 31;
    const int m0   = blockIdx.y << 7;
    const int n0   = blockIdx.x << 7;
    const int wm   = (w >> 2) * 64;           // warp row offset (2 rows of warps)
    const int wn   = (w & 3)  * 32;           // warp col offset (4 cols of warps)

    // global load assignment: thread handles row tid>>1, 16-col half tid&1
    const int arow = tid >> 1;
    const int acol = (tid & 1) * 16;
    const int gm   = m0 + arow;
    const size_t aoff = ((size_t)(gm / seg_len) * S_TOT + seg_off + (gm % seg_len)) * 1024 + acol;
    const size_t boff = ((size_t)(n0 + arow)) * 1024 + acol;

    float acc[4][4][4];
#pragma unroll
    for (int mt = 0; mt < 4; mt++)
#pragma unroll
        for (int nt = 0; nt < 4; nt++)
#pragma unroll
            for (int e = 0; e < 4; e++) acc[mt][nt][e] = 0.f;

    const int sdst = arow * GEMM_RS + acol;

    auto load_stage = [&](int s) {
        bf16* base = sm + (size_t)(s & 1) * 4 * GEMM_ARR;
        const int k0 = s << 5;
        const bf16* pAh = Ahi + aoff + k0;
        const bf16* pAl = Alo + aoff + k0;
        const bf16* pBh = Bhi + boff + k0;
        const bf16* pBl = Blo + boff + k0;
        bf16* d0 = base + sdst;
        *(uint4*)(d0)                    = *(const uint4*)(pAh);
        *(uint4*)(d0 + 8)                = *(const uint4*)(pAh + 8);
        *(uint4*)(d0 + GEMM_ARR)         = *(const uint4*)(pAl);
        *(uint4*)(d0 + GEMM_ARR + 8)     = *(const uint4*)(pAl + 8);
        *(uint4*)(d0 + 2 * GEMM_ARR)     = *(const uint4*)(pBh);
        *(uint4*)(d0 + 2 * GEMM_ARR + 8) = *(const uint4*)(pBh + 8);
        *(uint4*)(d0 + 3 * GEMM_ARR)     = *(const uint4*)(pBl);
        *(uint4*)(d0 + 3 * GEMM_ARR + 8) = *(const uint4*)(pBl + 8);
    };

    const int r  = lane >> 2;          // 0..7
    const int cq = (lane & 3) * 2;     // 0,2,4,6

    auto compute = [&](int s) {
        const bf16* base = sm + (size_t)(s & 1) * 4 * GEMM_ARR;
        const bf16* Ash = base;
        const bf16* Asl = base + GEMM_ARR;
        const bf16* Bsh = base + 2 * GEMM_ARR;
        const bf16* Bsl = base + 3 * GEMM_ARR;
#pragma unroll
        for (int kk = 0; kk < 32; kk += 16) {
            uint32_t ah[4][4], al[4][4], bh[4][2], bl[4][2];
#pragma unroll
            for (int mt = 0; mt < 4; mt++) {
                const int row = wm + mt * 16 + r;
                const bf16* ph = Ash + row * GEMM_RS + kk + cq;
                ah[mt][0] = *(const uint32_t*)(ph);
                ah[mt][1] = *(const uint32_t*)(ph + 8 * GEMM_RS);
                ah[mt][2] = *(const uint32_t*)(ph + 8);
                ah[mt][3] = *(const uint32_t*)(ph + 8 * GEMM_RS + 8);
                const bf16* pl = Asl + row * GEMM_RS + kk + cq;
                al[mt][0] = *(const uint32_t*)(pl);
                al[mt][1] = *(const uint32_t*)(pl + 8 * GEMM_RS);
                al[mt][2] = *(const uint32_t*)(pl + 8);
                al[mt][3] = *(const uint32_t*)(pl + 8 * GEMM_RS + 8);
            }
#pragma unroll
            for (int nt = 0; nt < 4; nt++) {
                const int col = wn + nt * 8 + r;
                const bf16* ph = Bsh + col * GEMM_RS + kk + cq;
                bh[nt][0] = *(const uint32_t*)(ph);
                bh[nt][1] = *(const uint32_t*)(ph + 8);
                const bf16* pl = Bsl + col * GEMM_RS + kk + cq;
                bl[nt][0] = *(const uint32_t*)(pl);
                bl[nt][1] = *(const uint32_t*)(pl + 8);
            }
#pragma unroll
            for (int mt = 0; mt < 4; mt++)
#pragma unroll
                for (int nt = 0; nt < 4; nt++) {
                    MMA_BF16(acc[mt][nt], ah[mt], bh[nt]);
                    MMA_BF16(acc[mt][nt], ah[mt], bl[nt]);
                    MMA_BF16(acc[mt][nt], al[mt], bh[nt]);
                }
        }
    };

    const int NS = 32;   // 1024 / 32
    load_stage(0);
    __syncthreads();
    for (int s = 0; s < NS; s++) {
        if (s + 1 < NS) load_stage(s + 1);
        compute(s);
        __syncthreads();
    }

    // ---- epilogue: direct stores, lane layout of m16n8 accum fragments
#pragma unroll
    for (int nt = 0; nt < 4; nt++) {
        const int col = n0 + wn + nt * 8 + cq;
        const float b0 = bias[col], b1 = bias[col + 1];
#pragma unroll
        for (int mt = 0; mt < 4; mt++) {
            const int row0 = m0 + wm + mt * 16 + r;
            float2 v0; v0.x = acc[mt][nt][0] + b0; v0.y = acc[mt][nt][1] + b1;
            float2 v1; v1.x = acc[mt][nt][2] + b0; v1.y = acc[mt][nt][3] + b1;
            *(float2*)(C + (size_t)row0 * N + col)       = v0;
            *(float2*)(C + (size_t)(row0 + 8) * N + col) = v1;
        }
    }
}

// ---------------------------------------------------------------------------
// split fp32 -> bf16 hi + bf16 lo (vectorized) — for hidden states
// ---------------------------------------------------------------------------
__global__ void split_kernel(const float* __restrict__ x, bf16* __restrict__ hi,
                             bf16* __restrict__ lo, int n4)
{
    for (int i = blockIdx.x * blockDim.x + threadIdx.x; i < n4; i += gridDim.x * blockDim.x) {
        float4 v = ((const float4*)x)[i];
        bf16 h0, h1, h2, h3, l0, l1, l2, l3;
        split_hl(v.x, h0, l0); split_hl(v.y, h1, l1);
        split_hl(v.z, h2, l2); split_hl(v.w, h3, l3);
        __nv_bfloat162* ph = (__nv_bfloat162*)hi;
        __nv_bfloat162* pl = (__nv_bfloat162*)lo;
        ph[2 * i]     = __nv_bfloat162(h0, h1);
        ph[2 * i + 1] = __nv_bfloat162(h2, h3);
        pl[2 * i]     = __nv_bfloat162(l0, l1);
        pl[2 * i + 1] = __nv_bfloat162(l2, l3);
    }
}

// ---------------------------------------------------------------------------
// transpose W[1024, N] -> Wt[N, 1024] with hi/lo bf16 split
// ---------------------------------------------------------------------------
__global__ __launch_bounds__(256)
void transpose_split(const float* __restrict__ W, int N,
                     bf16* __restrict__ Thi, bf16* __restrict__ Tlo)
{
    __shared__ float tile[32][33];
    const int tx = threadIdx.x, ty = threadIdx.y;
    const int n0 = blockIdx.x * 32, k0 = blockIdx.y * 32;
#pragma unroll
    for (int r = 0; r < 4; r++)
        tile[ty + 8 * r][tx] = W[(size_t)(k0 + ty + 8 * r) * N + n0 + tx];
    __syncthreads();
#pragma unroll
    for (int r = 0; r < 4; r++) {
        const float v = tile[tx][ty + 8 * r];
        bf16 h, l;
        split_hl(v, h, l);
        const size_t o = (size_t)(n0 + ty + 8 * r) * 1024 + k0 + tx;
        Thi[o] = h;
        Tlo[o] = l;
    }
}

// ---------------------------------------------------------------------------
// Dense causal attention over S0=1088 tokens. Emits ctx as hi/lo bf16 split.
// ---------------------------------------------------------------------------
__global__ __launch_bounds__(256)
void attn0_kernel(const float* __restrict__ qkv,
                  bf16* __restrict__ chi, bf16* __restrict__ clo)
{
    __shared__ float Ks[32][65];
    __shared__ float Vs[32][65];
    __shared__ float qs[8][66];
    __shared__ float ps[8][32];

    const int tid  = threadIdx.x;
    const int w    = tid >> 5, lane = tid & 31;
    const int qt   = blockIdx.x;
    const int h    = blockIdx.y;
    const int b    = blockIdx.z;

    const int qi = qt * 8 + w;
    const int c0 = lane * 2;

    {
        const float* qrow = qkv + ((size_t)(b * SS0 + qi)) * 3072 + h * 64;
        float2 qv = *(const float2*)(qrow + c0);
        qs[w][c0]     = qv.x * 0.125f;
        qs[w][c0 + 1] = qv.y * 0.125f;
    }
    __syncwarp();

    float m = -1e30f, l = 0.f, accx = 0.f, accy = 0.f;

    const int ntiles = (qt * 8 + 7) / 32 + 1;
    for (int t = 0; t < ntiles; t++) {
        const int j0 = t * 32;
        const float* kbase = qkv + ((size_t)(b * SS0 + j0)) * 3072 + 1024 + h * 64;
        const float* vbase = kbase + 1024;
        __syncthreads();
#pragma unroll
        for (int r = 0; r < 8; r++) {
            int idx = tid + (r << 8);
            int jj = idx >> 6, cc = idx & 63;
            Ks[jj][cc] = kbase[(size_t)jj * 3072 + cc];
            Vs[jj][cc] = vbase[(size_t)jj * 3072 + cc];
        }
        __syncthreads();

        float s = 0.f;
#pragma unroll
        for (int cc = 0; cc < 64; cc++) s += qs[w][cc] * Ks[lane][cc];
        const int jg = j0 + lane;
        const bool ok = (jg <= qi);
        if (!ok) s = -10000.f;

        float mt = s;
#pragma unroll
        for (int d = 16; d; d >>= 1) mt = fmaxf(mt, __shfl_xor_sync(~0u, mt, d));
        const float mnew = fmaxf(m, mt);
        const float p = ok ? __expf(s - mnew) : 0.f;
        const float scale = __expf(m - mnew);
        float pt = p;
#pragma unroll
        for (int d = 16; d; d >>= 1) pt += __shfl_xor_sync(~0u, pt, d);
        l = l * scale + pt;
        accx *= scale; accy *= scale;
        m = mnew;
        ps[w][lane] = p;
        __syncwarp();
#pragma unroll
        for (int jj = 0; jj < 32; jj++) {
            const float pj = ps[w][jj];
            accx += pj * Vs[jj][c0];
            accy += pj * Vs[jj][c0 + 1];
        }
        __syncwarp();
    }
    const float inv = 1.f / l;
    const float ox = accx * inv, oy = accy * inv;
    bf16 hx, lx, hy, ly;
    split_hl(ox, hx, lx);
    split_hl(oy, hy, ly);
    const size_t off = ((size_t)(b * S_TOT + qi)) * 1024 + h * 64 + c0;
    *(__nv_bfloat162*)(chi + off) = __nv_bfloat162(hx, hy);
    *(__nv_bfloat162*)(clo + off) = __nv_bfloat162(lx, ly);
}

// ---------------------------------------------------------------------------
// Local grid attention for the 64x64 tokens. Emits ctx as hi/lo bf16 split.
// ---------------------------------------------------------------------------
__global__ __launch_bounds__(256)
void attn1_kernel(const float* __restrict__ qkv0, const float* __restrict__ qkv1,
                  bf16* __restrict__ chi, bf16* __restrict__ clo)
{
    __shared__ float ss[8][128];

    const int tid  = threadIdx.x;
    const int w    = tid >> 5, lane = tid & 31;
    const int bh   = blockIdx.y;
    const int b    = bh >> 4, h = bh & 15;
    const int l    = blockIdx.x * 8 + w;
    const int i    = l >> 6, j = l & 63;
    const int c0   = lane * 2;

    float2 q = *(const float2*)(qkv1 + ((size_t)(b * SS1 + l)) * 3072 + h * 64 + c0);
    q.x *= 0.125f; q.y *= 0.125f;

    const float* k0base = qkv0 + ((size_t)(b * SS0 + 64)) * 3072 + 1024 + h * 64 + c0;
    const float* k1base = qkv1 + ((size_t)(b * SS1)) * 3072 + 1024 + h * 64 + c0;

    const int ci = i >> 1, cj = j >> 1;

    int o = 0;
    for (int dy = -3; dy <= 3; dy++)
        for (int dx = -3; dx <= 3; dx++, o++) {
            const int iy = ci + dy, ix = cj + dx;
            float s = 0.f;
            if ((unsigned)iy < 32u && (unsigned)ix < 32u) {
                const float2 kv = *(const float2*)(k0base + (size_t)(iy * 32 + ix) * 3072);
                s = q.x * kv.x + q.y * kv.y;
#pragma unroll
                for (int d = 16; d; d >>= 1) s += __shfl_xor_sync(~0u, s, d);
            }
            if (lane == 0) ss[w][o] = s;
        }
    for (int dy = -8; dy <= 0; dy++) {
        const int dxmax = (dy == 0) ? 0 : 4;
        for (int dx = -4; dx <= dxmax; dx++, o++) {
            const int iy = i + dy, ix = j + dx;
            float s = 0.f;
            if ((unsigned)iy < 64u && (unsigned)ix < 64u) {
                const float2 kv = *(const float2*)(k1base + (size_t)(iy * 64 + ix) * 3072);
                s = q.x * kv.x + q.y * kv.y;
#pragma unroll
                for (int d = 16; d; d >>= 1) s += __shfl_xor_sync(~0u, s, d);
            }
            if (lane == 0) ss[w][o] = s;
        }
    }
    __syncwarp();

    float sv[4];
#pragma unroll
    for (int g = 0; g < 4; g++) {
        const int oo = lane + 32 * g;
        sv[g] = (oo < 126) ? ss[w][oo] : -1e30f;
    }
    float mx = fmaxf(fmaxf(sv[0], sv[1]), fmaxf(sv[2], sv[3]));
#pragma unroll
    for (int d = 16; d; d >>= 1) mx = fmaxf(mx, __shfl_xor_sync(~0u, mx, d));
    float sum = 0.f, e[4];
#pragma unroll
    for (int g = 0; g < 4; g++) {
        const int oo = lane + 32 * g;
        e[g] = (oo < 126) ? __expf(sv[g] - mx) : 0.f;
        sum += e[g];
    }
#pragma unroll
    for (int d = 16; d; d >>= 1) sum += __shfl_xor_sync(~0u, sum, d);
    const float inv = 1.f / sum;
#pragma unroll
    for (int g = 0; g < 4; g++) {
        const int oo = lane + 32 * g;
        if (oo < 126) ss[w][oo] = e[g] * inv;
    }
    __syncwarp();

    const float* v0base = k0base + 1024;
    const float* v1base = k1base + 1024;
    float2 acc; acc.x = 0.f; acc.y = 0.f;
    o = 0;
    for (int dy = -3; dy <= 3; dy++)
        for (int dx = -3; dx <= 3; dx++, o++) {
            const int iy = ci + dy, ix = cj + dx;
            if ((unsigned)iy < 32u && (unsigned)ix < 32u) {
                const float p = ss[w][o];
                const float2 vv = *(const float2*)(v0base + (size_t)(iy * 32 + ix) * 3072);
                acc.x += p * vv.x;
                acc.y += p * vv.y;
            }
        }
    for (int dy = -8; dy <= 0; dy++) {
        const int dxmax = (dy == 0) ? 0 : 4;
        for (int dx = -4; dx <= dxmax; dx++, o++) {
            const int iy = i + dy, ix = j + dx;
            if ((unsigned)iy < 64u && (unsigned)ix < 64u) {
                const float p = ss[w][o];
                const float2 vv = *(const float2*)(v1base + (size_t)(iy * 64 + ix) * 3072);
                acc.x += p * vv.x;
                acc.y += p * vv.y;
            }
        }
    }

    bf16 hx, lx, hy, ly;
    split_hl(acc.x, hx, lx);
    split_hl(acc.y, hy, ly);
    const size_t off = ((size_t)(b * S_TOT + SS0 + l)) * 1024 + h * 64 + c0;
    *(__nv_bfloat162*)(chi + off) = __nv_bfloat162(hx, hy);
    *(__nv_bfloat162*)(clo + off) = __nv_bfloat162(lx, ly);
}

// ---------------------------------------------------------------------------
extern "C" void kernel_launch(void* const* d_in, const int* in_sizes, int n_in,
                              void* d_out, int out_size)
{
    const float* hidden  = (const float*)d_in[0];
    const float* W_qkv   = (const float*)d_in[2];
    const float* b_qkv   = (const float*)d_in[3];
    const float* W_qkvp  = (const float*)d_in[4];
    const float* b_qkvp  = (const float*)d_in[5];
    const float* W_dense = (const float*)d_in[6];
    const float* b_dense = (const float*)d_in[7];
    float* out = (float*)d_out;

    float *qkv0, *qkv1;
    bf16 *hid_hi, *hid_lo, *ctx_hi, *ctx_lo, *Wt_hi, *Wt_lo;
    cudaGetSymbolAddress((void**)&qkv0,   g_qkv0);
    cudaGetSymbolAddress((void**)&qkv1,   g_qkv1);
    cudaGetSymbolAddress((void**)&hid_hi, g_hid_hi);
    cudaGetSymbolAddress((void**)&hid_lo, g_hid_lo);
    cudaGetSymbolAddress((void**)&ctx_hi, g_ctx_hi);
    cudaGetSymbolAddress((void**)&ctx_lo, g_ctx_lo);
    cudaGetSymbolAddress((void**)&Wt_hi,  g_Wt_hi);
    cudaGetSymbolAddress((void**)&Wt_lo,  g_Wt_lo);

    // idempotent, not a stream op — safe under graph capture, no static guard
    cudaFuncSetAttribute(gemm_mma, cudaFuncAttributeMaxDynamicSharedMemorySize,
                         GEMM_SMEM_BYTES);

    const int nElem = BB * S_TOT * HH;       // 21,233,664 (mult of 4)

    // hidden -> hi/lo split ; weight transposes + split
    split_kernel<<<4096, 256>>>(hidden, hid_hi, hid_lo, nElem / 4);
    transpose_split<<<dim3(96, 32), dim3(32, 8)>>>(W_qkv,   3072, Wt_hi,               Wt_lo);
    transpose_split<<<dim3(96, 32), dim3(32, 8)>>>(W_qkvp,  3072, Wt_hi + 3072 * 1024, Wt_lo + 3072 * 1024);
    transpose_split<<<dim3(32, 32), dim3(32, 8)>>>(W_dense, 1024, Wt_hi + 6144 * 1024, Wt_lo + 6144 * 1024);

    // QKV projections (bf16 mma.sync tensor cores)
    gemm_mma<<<dim3(24, 34),  256, GEMM_SMEM_BYTES>>>(hid_hi, hid_lo, Wt_hi, Wt_lo,
                                                      b_qkv, qkv0, 3072, SS0, 0);
    gemm_mma<<<dim3(24, 128), 256, GEMM_SMEM_BYTES>>>(hid_hi, hid_lo,
                                                      Wt_hi + 3072 * 1024, Wt_lo + 3072 * 1024,
                                                      b_qkvp, qkv1, 3072, SS1, SS0);

    // Attention (emit ctx hi/lo directly — no separate split pass)
    attn0_kernel<<<dim3(136, 16, 4), 256>>>(qkv0, ctx_hi, ctx_lo);
    attn1_kernel<<<dim3(512, 64),    256>>>(qkv0, qkv1, ctx_hi, ctx_lo);

    // Output projection (bf16 mma.sync tensor cores)
    gemm_mma<<<dim3(8, 162), 256, GEMM_SMEM_BYTES>>>(ctx_hi, ctx_lo,
                                                     Wt_hi + 6144 * 1024, Wt_lo + 6144 * 1024,
                                                     b_dense, out, 1024, 1 << 30, 0);
}